// round 1
// baseline (speedup 1.0000x reference)
#include <cuda_runtime.h>

// Shapes (fixed by the problem): B=4, N=K=Q=5, L=31, D=512
// s: (4, 25, 31, 512)  q: (4, 25, 31, 512)
// wK: (150, 1024, K) for K=2,3,4,5 ; bK: (150,)
// Output: s_out (2500, 300) followed by q_out (2500, 300), fp32.
//
// Separability: conv over concat(s,q) channels splits into
//   y[(i,j),c,t] = As[i,c,t] + Aq[j,c,t]   (bias folded into As)
// Precompute As/Aq once (200 sequences), then combine over 2500 pairs.

#define DDIM   512
#define LSEQ   31
#define NC     150
#define WHALF  1075200   // 512 * 150 * (2+3+4+5)

// Transposed weights: [half(s/q)][conv-block][(d*K + kap)*150 + c]
__device__ float g_wt[2 * WHALF];
// A tensors: [type(0=s,1=q)*100 + seq][t(31)][cf(600)]  (cf = conv*150 + c)
__device__ float g_A[200 * 31 * 600];

// ---------------------------------------------------------------------------
// Weight transpose: w[c, cin, kap] -> g_wt[half][(d*K+kap)*150 + c]
// half = cin/512 (s-part vs q-part of the concat input channels)
// ---------------------------------------------------------------------------
__global__ void transpose_w_kernel(const float* __restrict__ w, int KK, int woff) {
    int idx = blockIdx.x * blockDim.x + threadIdx.x;
    int total = NC * 1024 * KK;
    if (idx >= total) return;
    int kap  = idx % KK;
    int rest = idx / KK;
    int cin  = rest % 1024;
    int c    = rest / 1024;
    int half = cin >> 9;
    int d    = cin & 511;
    g_wt[half * WHALF + woff + (d * KK + kap) * NC + c] = w[idx];
}

// ---------------------------------------------------------------------------
// Conv body: one (sequence, conv, t-half) per block, thread = out channel c.
// xs is the padded input window in smem: row r <-> l = t0 - 2 + r, 20 rows.
// y[t] = b[c] + sum_{kap,d} w[c,d,kap] * x[t + kap - PAD, d]
//   l = t + kap - PAD ; smem row = l - (t0-2) = (t - t0) + kap + (2 - PAD)
// ---------------------------------------------------------------------------
template<int KK, int PAD>
__device__ __forceinline__ void conv_body(const float (*xs)[DDIM], int type, int seq,
                                          int t0, const float* __restrict__ bias,
                                          int woff, int cfoff) {
    int c = threadIdx.x;
    if (c >= NC) return;
    const float* __restrict__ wp = g_wt + type * WHALF + woff;
    float binit = (type == 0) ? bias[c] : 0.f;
    float acc[16];
#pragma unroll
    for (int t = 0; t < 16; t++) acc[t] = binit;

    const int ROWOFF = 2 - PAD;
    for (int d = 0; d < DDIM; d++) {
        float wr[KK];
#pragma unroll
        for (int k = 0; k < KK; k++)
            wr[k] = wp[(d * KK + k) * NC + c];
        float xv[16 + KK - 1];
#pragma unroll
        for (int j = 0; j < 16 + KK - 1; j++)
            xv[j] = xs[j + ROWOFF][d];   // broadcast LDS (same addr across warp)
#pragma unroll
        for (int t = 0; t < 16; t++) {
#pragma unroll
            for (int k = 0; k < KK; k++)
                acc[t] = fmaf(wr[k], xv[t + k], acc[t]);
        }
    }

    // Write A[seq][t][cf] — coalesced across c
    float* ap = g_A + ((type * 100 + seq) * LSEQ) * 600 + cfoff + c;
#pragma unroll
    for (int t = 0; t < 16; t++) {
        int tt = t0 + t;
        if (tt < LSEQ) ap[tt * 600] = acc[t];
    }
}

__global__ void conv_all_kernel(const float* __restrict__ s, const float* __restrict__ q,
                                const float* __restrict__ b2, const float* __restrict__ b3,
                                const float* __restrict__ b4, const float* __restrict__ b5) {
    __shared__ float xs[20][DDIM];   // 40 KB: l window [t0-2, t0+17], zero-padded
    int seqg = blockIdx.x;           // 0..199 (0..99 = s, 100..199 = q)
    int type = seqg >= 100;
    int seq  = type ? seqg - 100 : seqg;
    int t0   = blockIdx.y * 16;      // 0 or 16

    const float* __restrict__ xg = (type ? q : s) + (size_t)seq * (LSEQ * DDIM);
    for (int e = threadIdx.x; e < 20 * DDIM; e += blockDim.x) {
        int r = e >> 9;
        int d = e & 511;
        int l = t0 - 2 + r;
        xs[r][d] = (l >= 0 && l < LSEQ) ? xg[l * DDIM + d] : 0.f;
    }
    __syncthreads();

    switch (blockIdx.z) {
        case 0: conv_body<2,1>(xs, type, seq, t0, b2, 0,      0);   break;
        case 1: conv_body<3,1>(xs, type, seq, t0, b3, 153600, 150); break;
        case 2: conv_body<4,2>(xs, type, seq, t0, b4, 384000, 300); break;
        case 3: conv_body<5,2>(xs, type, seq, t0, b5, 691200, 450); break;
    }
}

// ---------------------------------------------------------------------------
// Combine: for pair p = b*625 + i*25 + j, channel cf:
//   m = max(0, max_t (As[i,t,cf] + Aq[j,t,cf]))
// cf = conv*150 + c ; c<75 -> s_out[p, conv*75+c] ; else q_out[p, conv*75+c-75]
// ---------------------------------------------------------------------------
__global__ void combine_kernel(float* __restrict__ out) {
    int p   = blockIdx.x;            // 0..2499
    int b   = p / 625;
    int rem = p - b * 625;
    int i   = rem / 25;
    int j   = rem - i * 25;
    int cf  = threadIdx.x;           // 0..599

    const float* __restrict__ As = g_A + (size_t)(b * 25 + i) * (LSEQ * 600) + cf;
    const float* __restrict__ Aq = g_A + (size_t)(100 + b * 25 + j) * (LSEQ * 600) + cf;

    float m = 0.f;                   // relu folded into the max
#pragma unroll
    for (int t = 0; t < LSEQ; t++)
        m = fmaxf(m, As[t * 600] + Aq[t * 600]);

    int conv = cf / 150;
    int c    = cf - conv * 150;
    if (c < 75)
        out[p * 300 + conv * 75 + c] = m;
    else
        out[750000 + p * 300 + conv * 75 + (c - 75)] = m;
}

// ---------------------------------------------------------------------------
extern "C" void kernel_launch(void* const* d_in, const int* in_sizes, int n_in,
                              void* d_out, int out_size) {
    const float* s  = (const float*)d_in[0];
    const float* q  = (const float*)d_in[1];
    const float* w2 = (const float*)d_in[2];
    const float* b2 = (const float*)d_in[3];
    const float* w3 = (const float*)d_in[4];
    const float* b3 = (const float*)d_in[5];
    const float* w4 = (const float*)d_in[6];
    const float* b4 = (const float*)d_in[7];
    const float* w5 = (const float*)d_in[8];
    const float* b5 = (const float*)d_in[9];
    float* out = (float*)d_out;

    const int th = 256;
    transpose_w_kernel<<<(NC * 1024 * 2 + th - 1) / th, th>>>(w2, 2, 0);
    transpose_w_kernel<<<(NC * 1024 * 3 + th - 1) / th, th>>>(w3, 3, 153600);
    transpose_w_kernel<<<(NC * 1024 * 4 + th - 1) / th, th>>>(w4, 4, 384000);
    transpose_w_kernel<<<(NC * 1024 * 5 + th - 1) / th, th>>>(w5, 5, 691200);

    conv_all_kernel<<<dim3(200, 2, 4), 160>>>(s, q, b2, b3, b4, b5);

    combine_kernel<<<2500, 600>>>(out);
}